// round 11
// baseline (speedup 1.0000x reference)
#include <cuda_runtime.h>
#include <cuda_bf16.h>

// CenterLoss collapses: the label mask keeps only distmat[b, labels[b]]; all
// other B*(C-1) entries are 0 -> clamped to CLAMP_MIN.
// loss = (sum_b clamp(||x_b - c_{lbl_b}||^2, MIN, MAX)) / B + (C-1)*CLAMP_MIN.
// Labels are INT32 (established R2..R5).
//
// R11: SINGLE kernel, no cross-grid dependency. R8-R10 showed grid-completion
// propagation (what PDL's GridDependencySynchronize waits on) costs ~4.5us
// wherever it's placed. Here: blocks RED-add partial/B into g_acc, bump an
// acq_rel counter; last block writes out = g_acc + mask_term and resets g_acc
// (next replay ordered by the kernel boundary). Single wave (128 blocks) --
// R7's version of this idea ran 256 blocks = 2 waves + a 256-slot tail.

#define BATCH 4096
#define NUM_CLASSES 100000
#define FEAT_DIM 64
#define CLAMP_MIN_F 1e-12f
#define CLAMP_MAX_F 1e12f

#define BLOCK_THREADS 256
#define WARPS_PER_BLOCK 8
#define ROWS_PER_WARP 4
#define ROWS_PER_BLOCK (WARPS_PER_BLOCK * ROWS_PER_WARP)   // 32
#define NUM_BLOCKS (BATCH / ROWS_PER_BLOCK)                // 128 -> single wave

__device__ float        g_acc = 0.0f;         // reset by last block each call
__device__ unsigned int g_arrive_count = 0;   // reset by last block each call

__global__ void __launch_bounds__(BLOCK_THREADS)
center_loss_fused(const float* __restrict__ x,
                  const float* __restrict__ centers,
                  const int* __restrict__ labels,
                  float* __restrict__ out) {
    const int warp = threadIdx.x >> 5;
    const int lane = threadIdx.x & 31;
    const int row0 = blockIdx.x * ROWS_PER_BLOCK + warp * ROWS_PER_WARP;

    // One broadcast LDG.128 for this warp's 4 labels (row0 % 4 == 0).
    const int4 lraw = *reinterpret_cast<const int4*>(labels + row0);
    int lb[ROWS_PER_WARP] = {lraw.x, lraw.y, lraw.z, lraw.w};
    #pragma unroll
    for (int r = 0; r < ROWS_PER_WARP; r++) {
        // Crash guard (free): bad label -> wrong value, never a fault.
        lb[r] = (lb[r] < 0) ? 0 : (lb[r] >= NUM_CLASSES ? NUM_CLASSES - 1 : lb[r]);
    }

    // 8 independent 8B loads per lane; fully coalesced 256B rows.
    float2 xv[ROWS_PER_WARP], cv[ROWS_PER_WARP];
    #pragma unroll
    for (int r = 0; r < ROWS_PER_WARP; r++)
        xv[r] = reinterpret_cast<const float2*>(x + (size_t)(row0 + r) * FEAT_DIM)[lane];
    #pragma unroll
    for (int r = 0; r < ROWS_PER_WARP; r++)
        cv[r] = reinterpret_cast<const float2*>(centers + (size_t)lb[r] * FEAT_DIM)[lane];

    float a[ROWS_PER_WARP];
    #pragma unroll
    for (int r = 0; r < ROWS_PER_WARP; r++) {
        const float d0 = xv[r].x - cv[r].x;
        const float d1 = xv[r].y - cv[r].y;
        a[r] = d0 * d0 + d1 * d1;
    }

    #pragma unroll
    for (int o = 16; o > 0; o >>= 1) {
        #pragma unroll
        for (int r = 0; r < ROWS_PER_WARP; r++)
            a[r] += __shfl_xor_sync(0xffffffffu, a[r], o);
    }

    __shared__ float ws[WARPS_PER_BLOCK];
    if (lane == 0) {
        // clamp per ROW (clip-then-sum, faithful to reference), fixed order
        float s = 0.0f;
        #pragma unroll
        for (int r = 0; r < ROWS_PER_WARP; r++)
            s += fminf(fmaxf(a[r], CLAMP_MIN_F), CLAMP_MAX_F);
        ws[warp] = s;
    }
    __syncthreads();

    __shared__ bool s_is_last;
    if (threadIdx.x == 0) {
        float v = 0.0f;
        #pragma unroll
        for (int w = 0; w < WARPS_PER_BLOCK; w++) v += ws[w];
        // No-return float atomic -> REDG (~free at 128 ops, one address).
        atomicAdd(&g_acc, v * (1.0f / (float)BATCH));
        // acq_rel: release orders the RED above; acquire on the winner's side.
        unsigned int t;
        asm volatile("atom.add.acq_rel.gpu.global.u32 %0, [%1], 1;"
                     : "=r"(t) : "l"(&g_arrive_count) : "memory");
        s_is_last = (t == NUM_BLOCKS - 1);
    }
    // Only the winner block needs the flag; cheap block-wide sync.
    __syncthreads();

    if (s_is_last && threadIdx.x == 0) {
        // All 128 REDs happen-before counter==128 (each released by its bump).
        float total;
        asm volatile("ld.acquire.gpu.global.f32 %0, [%1];"
                     : "=f"(total) : "l"(&g_acc) : "memory");
        // (C-1) masked zeros per row -> CLAMP_MIN each; /B leaves (C-1)*MIN.
        const float mask_term = (float)(NUM_CLASSES - 1) * CLAMP_MIN_F;
        out[0] = total + mask_term;
        // Reset for next replay; ordered before next launch by kernel boundary.
        g_acc = 0.0f;
        g_arrive_count = 0;
    }
}

extern "C" void kernel_launch(void* const* d_in, const int* in_sizes, int n_in,
                              void* d_out, int out_size) {
    const float* x       = (const float*)d_in[0];
    const float* centers = (const float*)d_in[1];
    const int*   labels  = (const int*)d_in[2];
    float* out = (float*)d_out;

    center_loss_fused<<<NUM_BLOCKS, BLOCK_THREADS>>>(x, centers, labels, out);
}